// round 6
// baseline (speedup 1.0000x reference)
#include <cuda_runtime.h>
#include <cuda.h>
#include <cstdint>

// ---------------- problem constants ----------------
#define NN     10000
#define NPAD   10016
#define CC     128
#define NADJ   3
#define NSLOPE 0.2f

#define KCH     32
#define NCHUNK  ((NN + KCH - 1) / KCH)      // 313
#define NSPLIT  11
#define MTILES  ((NN + 127) / 128)          // 79
#define MPAD    (MTILES * 128)

#define BTILE_BYTES 16384                   // 128 x 32 fp32
#define STAGES_B    4
#define MIX_BYTES   16384
#define DYNSMEM     (STAGES_B * BTILE_BYTES + 2 * MIX_BYTES + 1024)

// scratch (static device arrays — zero-initialized, no allocation)
__device__ __align__(1024) float g_sup_t[CC * NPAD];           // supᵀ tf32, rotated layout
__device__ __align__(16)   float g_part[NSPLIT][MPAD][CC];     // split-K partials

// ---------------- helpers ----------------
__device__ __forceinline__ uint32_t smem_u32(const void* p) {
    uint32_t a;
    asm("{ .reg .u64 t; cvta.to.shared.u64 t, %1; cvt.u32.u64 %0, t; }" : "=r"(a) : "l"(p));
    return a;
}
__device__ __forceinline__ float tf32_rna_f(float x) {
    uint32_t u;
    asm("cvt.rna.tf32.f32 %0, %1;" : "=r"(u) : "f"(x));
    return __uint_as_float(u);
}
__device__ __forceinline__ uint32_t f2tf32(float x) {
    uint32_t u;
    asm("cvt.rna.tf32.f32 %0, %1;" : "=r"(u) : "f"(x));
    return u;
}
__device__ __forceinline__ void lds_b64(uint32_t a, uint32_t& lo, uint32_t& hi) {
    asm volatile("ld.shared.v2.b32 {%0, %1}, [%2];" : "=r"(lo), "=r"(hi) : "r"(a));
}
__device__ __forceinline__ void sts_b64(uint32_t a, uint32_t lo, uint32_t hi) {
    asm volatile("st.shared.v2.b32 [%0], {%1, %2};" :: "r"(a), "r"(lo), "r"(hi) : "memory");
}

#define MBARRIER_INIT(addr, cnt) \
    asm volatile("mbarrier.init.shared.b64 [%0], %1;" :: "r"(addr), "r"(cnt) : "memory")
#define MBARRIER_EXPECT_TX(addr, bytes) \
    asm volatile("mbarrier.arrive.expect_tx.shared.b64 _, [%0], %1;" :: "r"(addr), "r"(bytes) : "memory")
#define MBARRIER_ARRIVE(addr) \
    asm volatile("mbarrier.arrive.shared.b64 _, [%0];" :: "r"(addr) : "memory")

#define MBARRIER_WAIT_PARITY(mbar, par) do {                                      \
    uint32_t _m = (mbar), _p = (par), _d;                                         \
    asm volatile("{\n\t.reg .pred p;\n\t"                                         \
        "mbarrier.try_wait.parity.acquire.cta.shared::cta.b64 p, [%1], %2;\n\t"   \
        "selp.b32 %0, 1, 0, p;\n\t}" : "=r"(_d) : "r"(_m), "r"(_p) : "memory");   \
    if (!_d) {                                                                    \
        asm volatile("{\n\t.reg .pred P1;\n\t"                                    \
            "W_%=:\n\t"                                                           \
            "mbarrier.try_wait.parity.acquire.cta.shared::cta.b64 P1, [%0], %1, 0x989680;\n\t" \
            "@P1 bra.uni D_%=;\n\t"                                               \
            "bra.uni W_%=;\n\t"                                                   \
            "D_%=:\n\t}" :: "r"(_m), "r"(_p) : "memory");                         \
    } } while (0)

#define MBARRIER_WAIT_PARITY_RELAXED(mbar, par) do {                              \
    uint32_t _m = (mbar), _p = (par), _d;                                         \
    asm volatile("{\n\t.reg .pred p;\n\t"                                         \
        "mbarrier.try_wait.parity.relaxed.cta.shared::cta.b64 p, [%1], %2, 0x989680;\n\t" \
        "selp.b32 %0, 1, 0, p;\n\t}" : "=r"(_d) : "r"(_m), "r"(_p) : "memory");   \
    if (!_d) {                                                                    \
        asm volatile("{\n\t.reg .pred P1;\n\t"                                    \
            "W_%=:\n\t"                                                           \
            "mbarrier.try_wait.parity.relaxed.cta.shared::cta.b64 P1, [%0], %1, 0x989680;\n\t" \
            "@P1 bra.uni D_%=;\n\t"                                               \
            "bra.uni W_%=;\n\t"                                                   \
            "D_%=:\n\t}" :: "r"(_m), "r"(_p) : "memory");                         \
    } } while (0)

#define TMA_LOAD_3D(sa, tmap, x, y, z, mbar)                                      \
    asm volatile("cp.async.bulk.tensor.3d.shared::cta.global.tile.mbarrier::complete_tx::bytes " \
        "[%0], [%1, {%2, %3, %4}], [%5];"                                         \
        :: "r"((uint32_t)(sa)), "l"(tmap), "r"((int)(x)), "r"((int)(y)),          \
           "r"((int)(z)), "r"((uint32_t)(mbar)) : "memory")

// mma.sync m16n8k8 tf32 (baseline PTX)
__device__ __forceinline__ void mma_tf32(float* c, const uint32_t* A,
                                         uint32_t b0, uint32_t b1) {
    asm volatile(
        "mma.sync.aligned.m16n8k8.row.col.f32.tf32.tf32.f32 "
        "{%0,%1,%2,%3}, {%4,%5,%6,%7}, {%8,%9}, {%0,%1,%2,%3};"
        : "+f"(c[0]), "+f"(c[1]), "+f"(c[2]), "+f"(c[3])
        : "r"(A[0]), "r"(A[1]), "r"(A[2]), "r"(A[3]), "r"(b0), "r"(b1));
}

// ---------------- kernel 1: support = X@W + b ; rotated transposed tf32 copy -------
__global__ void __launch_bounds__(128)
k_support(const float* __restrict__ inp, const float* __restrict__ w,
          const float* __restrict__ b) {
    __shared__ float in_s[8][CC];
    __shared__ float s_out[CC][9];
    const int t  = threadIdx.x;
    const int n0 = blockIdx.x * 8;

    #pragma unroll
    for (int j = 0; j < 8; ++j)
        in_s[j][t] = inp[(n0 + j) * CC + t];
    __syncthreads();

    float acc[8];
    #pragma unroll
    for (int j = 0; j < 8; ++j) acc[j] = 0.f;
    const float bc = b[t];
    #pragma unroll 4
    for (int i = 0; i < CC; ++i) {
        const float wv = w[i * CC + t];
        #pragma unroll
        for (int j = 0; j < 8; ++j) acc[j] = fmaf(in_s[j][i], wv, acc[j]);
    }
    #pragma unroll
    for (int j = 0; j < 8; ++j) s_out[t][j] = acc[j] + bc;
    __syncthreads();

    const int j2 = t & 7;
    const int c0 = t >> 3;
    const int nloc  = (n0 & 31) | j2;
    const int ks    = nloc >> 3;
    const int p     = nloc & 3;
    const int hi    = (nloc >> 2) & 1;
    const int nbase = n0 & ~31;
    #pragma unroll
    for (int cc = 0; cc < CC; cc += 16) {
        const int c = cc + c0;
        const int perm = (((ks + c) & 3) << 3) | ((2 * p + 2 * c) & 6) | hi;
        g_sup_t[c * NPAD + nbase + perm] = tf32_rna_f(s_out[c][j2]);
    }
}

// ---------------- kernel 2: split-K tf32 HMMA GEMM, LDG-register premix ------------
__global__ void __launch_bounds__(512, 1)
k_gemm(const __grid_constant__ CUtensorMap tmap_b,
       const float* __restrict__ adj,
       const float* __restrict__ att) {
    extern __shared__ __align__(1024) char dsm[];
    __shared__ __align__(8) uint64_t bars[2 * STAGES_B];

    const int tid  = threadIdx.x;
    const int wid  = tid >> 5;
    const int lane = tid & 31;
    const int g    = lane >> 2;
    const int q    = lane & 3;
    const int m0   = blockIdx.x * 128;
    const int sidx = blockIdx.y;

    const uint32_t dbase   = (smem_u32(dsm) + 1023u) & ~1023u;
    const uint32_t mixbase = dbase + STAGES_B * BTILE_BYTES;
    const uint32_t barb    = smem_u32(bars);

    if (tid == 0) {
        for (int s = 0; s < STAGES_B; ++s) {
            MBARRIER_INIT(barb + 8 * s, 1);
            MBARRIER_INIT(barb + 8 * (STAGES_B + s), 512);
        }
        asm volatile("fence.proxy.async.shared::cta;" ::: "memory");
    }
    __syncthreads();

    const float at0 = att[0], at1 = att[1], at2 = att[2];
    const int nch = (NCHUNK - sidx + NSPLIT - 1) / NSPLIT;

    // ---- B producer prologue ----
    if (tid == 0) {
        int pre = (nch < STAGES_B) ? nch : STAGES_B;
        for (int i = 0; i < pre; ++i) {
            uint32_t fb = barb + 8 * i;
            MBARRIER_EXPECT_TX(fb, (uint32_t)BTILE_BYTES);
            TMA_LOAD_3D(dbase + i * BTILE_BYTES, &tmap_b,
                        (sidx + i * NSPLIT) * KCH, 0, 0, fb);
        }
    }

    // premix thread mapping: row r = tid>>2, k-quarter q = tid&3
    const int pr = tid >> 2;                       // 0..127
    const int mrow = (m0 + pr < NN) ? (m0 + pr) : (NN - 1);   // clamp OOB rows
    const float* arow = adj + (size_t)mrow * NN;
    const int ksA = q >> 1;                        // own ks (group1)
    const int phi = q & 1;                         // own hi
    // this thread writes blocks wks (4 STS.64): hi0-threads write ksA, hi1 write ksA+2
    const int wks = phi ? (ksA + 2) : ksA;
    const uint32_t sts_base = (uint32_t)pr * 32 + (uint32_t)(((wks + pr) & 3) << 3);
    const uint32_t slot_rot = (uint32_t)(2 * pr);

    // warp tiling: 16 warps = 4 (M) x 4 (N)
    const int wm = wid & 3;
    const int wn = wid >> 2;

    float acc[2][4][4];
    #pragma unroll
    for (int mi = 0; mi < 2; ++mi)
        #pragma unroll
        for (int ni = 0; ni < 4; ++ni)
            #pragma unroll
            for (int r = 0; r < 4; ++r) acc[mi][ni][r] = 0.f;

    // ---- LDG prefetch of chunk 0 ----
    float4 pf1[NADJ], pf2[NADJ];
    {
        const int k0 = sidx * KCH;
        const bool tail = (k0 + KCH > NN);
        #pragma unroll
        for (int t = 0; t < NADJ; ++t) {
            const float* p0 = arow + (size_t)t * NN * NN + k0 + 4 * q;
            pf1[t] = *reinterpret_cast<const float4*>(p0);
            pf2[t] = tail ? make_float4(0.f, 0.f, 0.f, 0.f)
                          : *reinterpret_cast<const float4*>(p0 + 16);
        }
    }

    for (int it = 0; it < nch; ++it) {
        const int s  = it % STAGES_B;
        const int ph = (it / STAGES_B) & 1;
        const uint32_t Bb   = dbase + s * BTILE_BYTES;
        const uint32_t mixb = mixbase + (uint32_t)(it & 1) * MIX_BYTES;

        // ---- premix in registers: mv1 = own-(ksA,hi) group, mv2 = (ksA+2,hi) ----
        float mv1[4], mv2[4];
        #pragma unroll
        for (int i = 0; i < 4; ++i) {
            const float* x1 = &pf1[0].x;  // float4 laid out contiguously
            mv1[i] = fmaf(at2, (&pf1[2].x)[i], fmaf(at1, (&pf1[1].x)[i], at0 * (&pf1[0].x)[i]));
            mv2[i] = fmaf(at2, (&pf2[2].x)[i], fmaf(at1, (&pf2[1].x)[i], at0 * (&pf2[0].x)[i]));
            (void)x1;
        }
        // exchange with partner lane (q^1): partner has same ks pair, other hi
        float sv1[4], sv2[4];
        #pragma unroll
        for (int i = 0; i < 4; ++i) {
            sv1[i] = __shfl_xor_sync(0xFFFFFFFFu, mv1[i], 1);
            sv2[i] = __shfl_xor_sync(0xFFFFFFFFu, mv2[i], 1);
        }
        // hi0-thread: writes (ksA): lo=own mv1 (hi0), hi=partner sv1 (hi1)
        // hi1-thread: writes (ksA+2): lo=partner sv2 (hi0), hi=own mv2 (hi1)
        #pragma unroll
        for (int i = 0; i < 4; ++i) {
            const float lo = phi ? sv2[i] : mv1[i];
            const float hh = phi ? mv2[i] : sv1[i];
            const uint32_t pos = sts_base + ((slot_rot + 2 * (uint32_t)i) & 6);
            sts_b64(mixb + pos * 4, f2tf32(lo), f2tf32(hh));
        }

        // ---- LDG prefetch next chunk ----
        if (it + 1 < nch) {
            const int k0n = (sidx + (it + 1) * NSPLIT) * KCH;
            const bool tail = (k0n + KCH > NN);
            #pragma unroll
            for (int t = 0; t < NADJ; ++t) {
                const float* p0 = arow + (size_t)t * NN * NN + k0n + 4 * q;
                pf1[t] = *reinterpret_cast<const float4*>(p0);
                pf2[t] = tail ? make_float4(0.f, 0.f, 0.f, 0.f)
                              : *reinterpret_cast<const float4*>(p0 + 16);
            }
        }

        __syncthreads();                       // mixed tile visible
        MBARRIER_WAIT_PARITY(barb + 8 * s, ph); // B tile ready

        // ---- MMA phase ----
        #pragma unroll
        for (int ks = 0; ks < 4; ++ks) {
            const uint32_t koff = (uint32_t)(((((ks + g) & 3) << 3)) | ((2 * q + 2 * g) & 6));
            uint32_t amix[2][4];
            #pragma unroll
            for (int mi = 0; mi < 2; ++mi) {
                const uint32_t wa = ((uint32_t)(wm * 32 + mi * 16 + g) * 32) + koff;
                lds_b64(mixb + wa * 4,         amix[mi][0], amix[mi][2]);
                lds_b64(mixb + (wa + 256) * 4, amix[mi][1], amix[mi][3]);
            }
            const uint32_t kb = koff ^ ((uint32_t)g << 2);
            #pragma unroll
            for (int ni = 0; ni < 4; ++ni) {
                const uint32_t wb = ((uint32_t)(wn * 32 + ni * 8 + g) * 32) + kb;
                uint32_t b0, b1;
                lds_b64(Bb + wb * 4, b0, b1);
                mma_tf32(acc[0][ni], amix[0], b0, b1);
                mma_tf32(acc[1][ni], amix[1], b0, b1);
            }
        }

        MBARRIER_ARRIVE(barb + 8 * (STAGES_B + s));

        if (tid == 0 && it + STAGES_B < nch) {
            MBARRIER_WAIT_PARITY_RELAXED(barb + 8 * (STAGES_B + s), (it / STAGES_B) & 1);
            uint32_t fb = barb + 8 * s;
            MBARRIER_EXPECT_TX(fb, (uint32_t)BTILE_BYTES);
            TMA_LOAD_3D(Bb, &tmap_b, (sidx + (it + STAGES_B) * NSPLIT) * KCH, 0, 0, fb);
        }
    }

    // ---- write split-K partials ----
    float* pbase = &g_part[sidx][0][0];
    #pragma unroll
    for (int mi = 0; mi < 2; ++mi) {
        #pragma unroll
        for (int ni = 0; ni < 4; ++ni) {
            const int r = m0 + wm * 32 + mi * 16 + g;
            const int c = wn * 32 + ni * 8 + q * 2;
            float2 v0 = make_float2(acc[mi][ni][0], acc[mi][ni][1]);
            float2 v1 = make_float2(acc[mi][ni][2], acc[mi][ni][3]);
            *reinterpret_cast<float2*>(pbase + (size_t)r * CC + c)       = v0;
            *reinterpret_cast<float2*>(pbase + (size_t)(r + 8) * CC + c) = v1;
        }
    }
}

// ---------------- kernel 3: reduce split-K partials + LeakyReLU --------------------
__global__ void __launch_bounds__(256)
k_reduce(float* __restrict__ out) {
    const int idx = blockIdx.x * 256 + threadIdx.x;
    const int total = NN * CC / 4;
    if (idx >= total) return;
    const int n  = idx / (CC / 4);
    const int c4 = (idx % (CC / 4)) * 4;

    float4 s = make_float4(0.f, 0.f, 0.f, 0.f);
    #pragma unroll
    for (int k = 0; k < NSPLIT; ++k) {
        const float4 v = *reinterpret_cast<const float4*>(&g_part[k][n][c4]);
        s.x += v.x; s.y += v.y; s.z += v.z; s.w += v.w;
    }
    s.x = (s.x >= 0.f) ? s.x : NSLOPE * s.x;
    s.y = (s.y >= 0.f) ? s.y : NSLOPE * s.y;
    s.z = (s.z >= 0.f) ? s.z : NSLOPE * s.z;
    s.w = (s.w >= 0.f) ? s.w : NSLOPE * s.w;
    *reinterpret_cast<float4*>(&out[(size_t)n * CC + c4]) = s;
}

// dummies: position k_gemm as 4th launch (6th overall) so ncu -s 5 -c 1 profiles it
__global__ void k_dummy() {}
__global__ void k_dummy2() {}

// ---------------- host launch ----------------
typedef CUresult (*PFN_encodeTiled)(
    CUtensorMap*, CUtensorMapDataType, cuuint32_t, void*,
    const cuuint64_t*, const cuuint64_t*, const cuuint32_t*, const cuuint32_t*,
    CUtensorMapInterleave, CUtensorMapSwizzle, CUtensorMapL2promotion,
    CUtensorMapFloatOOBfill);

extern "C" void kernel_launch(void* const* d_in, const int* in_sizes, int n_in,
                              void* d_out, int out_size) {
    const float *inp = nullptr, *adj = nullptr, *att = nullptr, *w = nullptr, *b = nullptr;
    for (int i = 0; i < n_in; ++i) {
        switch (in_sizes[i]) {
            case NN * CC:        inp = (const float*)d_in[i]; break;
            case NADJ * NN * NN: adj = (const float*)d_in[i]; break;
            case NADJ:           att = (const float*)d_in[i]; break;
            case CC * CC:        w   = (const float*)d_in[i]; break;
            case CC:             b   = (const float*)d_in[i]; break;
            default: break;
        }
    }
    float* out = (float*)d_out;

    k_support<<<NN / 8, 128>>>(inp, w, b);
    k_dummy<<<1, 32>>>();
    k_dummy2<<<1, 32>>>();

    PFN_encodeTiled enc = nullptr;
    {
        void* p = nullptr;
        cudaDriverEntryPointQueryResult st;
#if CUDART_VERSION >= 12050
        cudaGetDriverEntryPointByVersion("cuTensorMapEncodeTiled", &p, 12000,
                                         cudaEnableDefault, &st);
#else
        cudaGetDriverEntryPoint("cuTensorMapEncodeTiled", &p, cudaEnableDefault, &st);
#endif
        enc = (PFN_encodeTiled)p;
    }
    void* supt_ptr = nullptr;
    cudaGetSymbolAddress(&supt_ptr, g_sup_t);

    CUtensorMap tb;
    cuuint32_t box[3] = {KCH, 128, 1};
    cuuint32_t es[3]  = {1, 1, 1};
    {   // B: g_sup_t [CC][NPAD] (rotated layout), inner dim = K
        cuuint64_t dims[3] = {NPAD, CC, 1};
        cuuint64_t str[2]  = {(cuuint64_t)NPAD * 4, (cuuint64_t)CC * NPAD * 4};
        enc(&tb, CU_TENSOR_MAP_DATA_TYPE_FLOAT32, 3, supt_ptr, dims, str, box, es,
            CU_TENSOR_MAP_INTERLEAVE_NONE, CU_TENSOR_MAP_SWIZZLE_128B,
            CU_TENSOR_MAP_L2_PROMOTION_L2_128B, CU_TENSOR_MAP_FLOAT_OOB_FILL_NONE);
    }

    cudaFuncSetAttribute(k_gemm, cudaFuncAttributeMaxDynamicSharedMemorySize, DYNSMEM);
    dim3 grid(MTILES, NSPLIT);
    k_gemm<<<grid, 512, DYNSMEM>>>(tb, adj, att);

    k_reduce<<<(NN * CC / 4 + 255) / 256, 256>>>(out);
}